// round 5
// baseline (speedup 1.0000x reference)
#include <cuda_runtime.h>
#include <mma.h>
#include <math.h>
using namespace nvcuda;

// Problem dims
#define Bb 16
#define Ss 64
#define Rr 6
#define Ll 24
#define Dd 128
#define Hh 256
#define BS 1024      // B*S
#define NSEQ 6144    // B*S*R
#define NROWS_XW (NSEQ * Ll)   // 147456

// ---------------- scratch (device globals; no allocations allowed) ----------------
__device__ float g_Whh_i[768 * 256];     // interleaved: row 3j+g = w_hh[g*256+j]
__device__ float g_Wih_i[768 * 128];     // interleaved: row 3j+g = w_ih[g*256+j]
__device__ float g_bias_i[2 * 768];      // [0:768) b_ih interleaved, [768:1536) b_hh
__device__ float g_xw_inter[(size_t)NROWS_XW * 768];  // interleaved gates
__device__ float g_xw_intra[BS * 768];                // interleaved gates
__device__ float g_hA[NSEQ * Hh];
__device__ float g_hB[NSEQ * Hh];
__device__ float g_his_last[NSEQ * Hh];
__device__ float g_intra_h[BS * Hh];
__device__ float g_Mrv[NSEQ * 384];
__device__ float g_mpv[BS * 384];
__device__ float g_hp[BS * 288];
__device__ float g_qi[BS * Hh];
__device__ float g_ki[NSEQ * Hh];
__device__ float g_vi[NSEQ * Hh];
__device__ float g_oi[BS * Hh];
__device__ float g_vv[BS * Hh];
__device__ float g_qh[BS * Hh];
__device__ float g_kh[BS * Hh];
__device__ float g_vhp[BS * Hh];
__device__ float g_oh[BS * Hh];
__device__ float g_vh[BS * Hh];
__device__ float g_feat[BS * 640];
__device__ float g_Wq[256 * 384];
__device__ float g_Wk[256 * 384];
__device__ float g_Waq[256 * 128];
__device__ float g_Wak[256 * 128];
__device__ float g_Wav[256 * 288];
__device__ float g_Wln[256 * 640];

__device__ __forceinline__ float sigmoidf_(float x) { return 1.f / (1.f + expf(-x)); }

// ---------------- weight interleaving / padding ----------------
__global__ void prep_whh_i(const float* __restrict__ w_hh, float* __restrict__ dst) {
    int idx = blockIdx.x * blockDim.x + threadIdx.x;
    if (idx >= 768 * 256) return;
    int row = idx >> 8, k = idx & 255;
    int j = row / 3, g = row % 3;
    dst[idx] = w_hh[(g * 256 + j) * 256 + k];
}
__global__ void prep_wih_i(const float* __restrict__ w_ih, float* __restrict__ dst) {
    int idx = blockIdx.x * blockDim.x + threadIdx.x;
    if (idx >= 768 * 128) return;
    int row = idx >> 7, k = idx & 127;
    int j = row / 3, g = row % 3;
    dst[idx] = w_ih[(g * 256 + j) * 128 + k];
}
__global__ void prep_bias_i(const float* __restrict__ b_ih, const float* __restrict__ b_hh,
                            float* __restrict__ dst) {
    int idx = blockIdx.x * blockDim.x + threadIdx.x;
    if (idx >= 768) return;
    int j = idx / 3, g = idx % 3;
    dst[idx] = b_ih[g * 256 + j];
    dst[768 + idx] = b_hh[g * 256 + j];
}
__global__ void pad_w(const float* __restrict__ src, float* __restrict__ dst,
                      int N, int Ks, int Kd) {
    int idx = blockIdx.x * blockDim.x + threadIdx.x;
    if (idx >= N * Kd) return;
    int n = idx / Kd, k = idx % Kd;
    dst[idx] = (k < Ks) ? src[n * Ks + k] : 0.f;
}

// ---------------- wide tf32 GEMM: tile 64x192, 8 warps (2x4), warp 32x48 -----------
__global__ void __launch_bounds__(256) gemm_tc_wide(
    int M, int K,
    const float* __restrict__ A, int lda,
    const float* __restrict__ W, int ldw,   // W rows = N (interleaved or plain), ldw=K
    float* __restrict__ C, int ldc)
{
    __shared__ float smem[64 * 36 + 192 * 36];
    float* As = smem;                 // [64][36]
    float* Bs = smem + 64 * 36;      // [192][36]
    float* Cs = smem;                // [32][196] per pass

    int i0 = blockIdx.x * 64, n0 = blockIdx.y * 192;
    int tid = threadIdx.x;
    int warp = tid >> 5, wy = warp >> 2, wx = warp & 3;

    wmma::fragment<wmma::accumulator, 16, 16, 8, float> acc[2][3];
#pragma unroll
    for (int a = 0; a < 2; a++)
#pragma unroll
        for (int b = 0; b < 3; b++) wmma::fill_fragment(acc[a][b], 0.f);

    for (int k0 = 0; k0 < K; k0 += 32) {
#pragma unroll
        for (int it = 0; it < 2; it++) {
            int idx = tid + it * 256;
            int r = idx >> 3, k4 = (idx & 7) << 2;
            float4 v = make_float4(0.f, 0.f, 0.f, 0.f);
            if (i0 + r < M) v = *(const float4*)(A + (size_t)(i0 + r) * lda + k0 + k4);
            *(float4*)(As + r * 36 + k4) = v;
        }
#pragma unroll
        for (int it = 0; it < 6; it++) {
            int idx = tid + it * 256;
            int c = idx >> 3, k4 = (idx & 7) << 2;
            float4 v = *(const float4*)(W + (size_t)(n0 + c) * ldw + k0 + k4);
            *(float4*)(Bs + c * 36 + k4) = v;
        }
        __syncthreads();
#pragma unroll
        for (int kk = 0; kk < 32; kk += 8) {
            wmma::fragment<wmma::matrix_a, 16, 16, 8, wmma::precision::tf32, wmma::row_major> af[2];
            wmma::fragment<wmma::matrix_b, 16, 16, 8, wmma::precision::tf32, wmma::col_major> bf[3];
#pragma unroll
            for (int fy = 0; fy < 2; fy++) {
                wmma::load_matrix_sync(af[fy], As + (wy * 32 + fy * 16) * 36 + kk, 36);
#pragma unroll
                for (int e = 0; e < af[fy].num_elements; e++)
                    af[fy].x[e] = wmma::__float_to_tf32(af[fy].x[e]);
            }
#pragma unroll
            for (int fx = 0; fx < 3; fx++) {
                wmma::load_matrix_sync(bf[fx], Bs + (wx * 48 + fx * 16) * 36 + kk, 36);
#pragma unroll
                for (int e = 0; e < bf[fx].num_elements; e++)
                    bf[fx].x[e] = wmma::__float_to_tf32(bf[fx].x[e]);
            }
#pragma unroll
            for (int fy = 0; fy < 2; fy++)
#pragma unroll
                for (int fx = 0; fx < 3; fx++)
                    wmma::mma_sync(acc[fy][fx], af[fy], bf[fx], acc[fy][fx]);
        }
        __syncthreads();
    }

    for (int pass = 0; pass < 2; pass++) {
        __syncthreads();
        if (wy == pass) {
#pragma unroll
            for (int fy = 0; fy < 2; fy++)
#pragma unroll
                for (int fx = 0; fx < 3; fx++)
                    wmma::store_matrix_sync(Cs + (fy * 16) * 196 + wx * 48 + fx * 16,
                                            acc[fy][fx], 196, wmma::mem_row_major);
        }
        __syncthreads();
#pragma unroll
        for (int it = 0; it < 6; it++) {
            int idx = tid + it * 256;
            int row = idx / 48, c4 = (idx % 48) << 2;
            int gi = i0 + pass * 32 + row;
            if (gi >= M) continue;
            float4 v = *(float4*)(Cs + row * 196 + c4);
            *(float4*)(C + (size_t)gi * ldc + n0 + c4) = v;
        }
    }
}

// ---------------- fused recurrent GEMM + GRU gate ----------------
// gh = h_prev @ Whh_i^T over interleaved gate rows; gate epilogue in-block.
// Tile 64 rows x 192 cols (= 64 units x 3 gates). All 8 warps MMA-active.
__global__ void __launch_bounds__(256) gru_fused_step(
    int t,
    const float* __restrict__ Whh_i,
    const float* __restrict__ xw,          // interleaved, row (i*Ll + t)
    const float* __restrict__ bias_i,
    const int* __restrict__ lenp,
    const float* __restrict__ h_prev, float* __restrict__ h_out,
    float* __restrict__ his_last)
{
    __shared__ float smem[64 * 36 + 192 * 36];
    float* As = smem;
    float* Bs = smem + 64 * 36;
    float* Cs = smem;                // [32][196]

    const int i0 = blockIdx.x * 64;
    const int n0 = blockIdx.y * 192;       // = 3 * j0, j0 = blockIdx.y*64
    const int tid = threadIdx.x;
    const int warp = tid >> 5, wy = warp >> 2, wx = warp & 3;

    wmma::fragment<wmma::accumulator, 16, 16, 8, float> acc[2][3];
#pragma unroll
    for (int a = 0; a < 2; a++)
#pragma unroll
        for (int b = 0; b < 3; b++) wmma::fill_fragment(acc[a][b], 0.f);

    if (t > 0) {
        for (int k0 = 0; k0 < 256; k0 += 32) {
#pragma unroll
            for (int it = 0; it < 2; it++) {
                int idx = tid + it * 256;
                int r = idx >> 3, k4 = (idx & 7) << 2;
                float4 v = *(const float4*)(h_prev + (size_t)(i0 + r) * 256 + k0 + k4);
                *(float4*)(As + r * 36 + k4) = v;
            }
#pragma unroll
            for (int it = 0; it < 6; it++) {
                int idx = tid + it * 256;
                int c = idx >> 3, k4 = (idx & 7) << 2;
                float4 v = *(const float4*)(Whh_i + (size_t)(n0 + c) * 256 + k0 + k4);
                *(float4*)(Bs + c * 36 + k4) = v;
            }
            __syncthreads();
#pragma unroll
            for (int kk = 0; kk < 32; kk += 8) {
                wmma::fragment<wmma::matrix_a, 16, 16, 8, wmma::precision::tf32, wmma::row_major> af[2];
                wmma::fragment<wmma::matrix_b, 16, 16, 8, wmma::precision::tf32, wmma::col_major> bf[3];
#pragma unroll
                for (int fy = 0; fy < 2; fy++) {
                    wmma::load_matrix_sync(af[fy], As + (wy * 32 + fy * 16) * 36 + kk, 36);
#pragma unroll
                    for (int e = 0; e < af[fy].num_elements; e++)
                        af[fy].x[e] = wmma::__float_to_tf32(af[fy].x[e]);
                }
#pragma unroll
                for (int fx = 0; fx < 3; fx++) {
                    wmma::load_matrix_sync(bf[fx], Bs + (wx * 48 + fx * 16) * 36 + kk, 36);
#pragma unroll
                    for (int e = 0; e < bf[fx].num_elements; e++)
                        bf[fx].x[e] = wmma::__float_to_tf32(bf[fx].x[e]);
                }
#pragma unroll
                for (int fy = 0; fy < 2; fy++)
#pragma unroll
                    for (int fx = 0; fx < 3; fx++)
                        wmma::mma_sync(acc[fy][fx], af[fy], bf[fx], acc[fy][fx]);
            }
            __syncthreads();
        }
    }

    // ---- gate epilogue, two 32-row passes
    for (int pass = 0; pass < 2; pass++) {
        __syncthreads();
        if (wy == pass) {
#pragma unroll
            for (int fy = 0; fy < 2; fy++)
#pragma unroll
                for (int fx = 0; fx < 3; fx++)
                    wmma::store_matrix_sync(Cs + (fy * 16) * 196 + wx * 48 + fx * 16,
                                            acc[fy][fx], 196, wmma::mem_row_major);
        }
        __syncthreads();
#pragma unroll
        for (int it = 0; it < 8; it++) {
            int idx = tid + it * 256;      // 2048 = 32 rows x 64 units
            int row = idx >> 6, jl = idx & 63;
            int gi = i0 + pass * 32 + row;
            int c = 3 * jl;                // interleaved offset within tile
            int j = (n0 / 3) + jl;         // global unit
            float ghr = Cs[row * 196 + c];
            float ghz = Cs[row * 196 + c + 1];
            float ghn = Cs[row * 196 + c + 2];
            const float* xwrow = xw + ((size_t)gi * Ll + t) * 768 + n0 + c;
            float xr = xwrow[0], xz = xwrow[1], xn = xwrow[2];
            float bir = bias_i[n0 + c],      biz = bias_i[n0 + c + 1],      bin = bias_i[n0 + c + 2];
            float bhr = bias_i[768 + n0 + c], bhz = bias_i[768 + n0 + c + 1], bhn = bias_i[768 + n0 + c + 2];
            float hp = (t > 0) ? h_prev[(size_t)gi * 256 + j] : 0.f;
            float r = sigmoidf_(xr + bir + ghr + bhr);
            float z = sigmoidf_(xz + biz + ghz + bhz);
            float n = tanhf(xn + bin + r * (ghn + bhn));
            float h = (1.f - z) * n + z * hp;
            h_out[(size_t)gi * 256 + j] = h;
            if (lenp[gi] == t + 1) his_last[(size_t)gi * 256 + j] = h;
        }
        __syncthreads();
    }
}

// ---------------- tf32 tensor-core GEMM (tile 128x64): C = A @ W^T + bias ----------
__global__ void __launch_bounds__(256) gemm_tc(
    int M, int N, int K,
    const float* __restrict__ A, int lda,
    const float* __restrict__ W, int ldw,
    const float* __restrict__ bias,
    float* __restrict__ C, int ldc)
{
    __shared__ float smem[128 * 68];
    float* As = smem;
    float* Bs = smem + 128 * 40;

    int i0 = blockIdx.x * 128, n0 = blockIdx.y * 64;
    int tid = threadIdx.x;
    int warp = tid >> 5;
    int wy = warp >> 1, wx = warp & 1;

    wmma::fragment<wmma::accumulator, 16, 16, 8, float> acc[2][2];
#pragma unroll
    for (int a = 0; a < 2; a++)
#pragma unroll
        for (int b = 0; b < 2; b++) wmma::fill_fragment(acc[a][b], 0.f);

    for (int k0 = 0; k0 < K; k0 += 32) {
#pragma unroll
        for (int it = 0; it < 4; it++) {
            int idx = tid + it * 256;
            int r = idx >> 3, k4 = (idx & 7) << 2;
            float4 v = make_float4(0.f, 0.f, 0.f, 0.f);
            int gi = i0 + r;
            if (gi < M) v = *(const float4*)(A + (size_t)gi * lda + k0 + k4);
            *(float4*)(As + r * 40 + k4) = v;
        }
#pragma unroll
        for (int it = 0; it < 2; it++) {
            int idx = tid + it * 256;
            int n = idx >> 3, k4 = (idx & 7) << 2;
            float4 v = *(const float4*)(W + (size_t)(n0 + n) * ldw + k0 + k4);
            *(float4*)(Bs + n * 40 + k4) = v;
        }
        __syncthreads();
#pragma unroll
        for (int kk = 0; kk < 32; kk += 8) {
            wmma::fragment<wmma::matrix_a, 16, 16, 8, wmma::precision::tf32, wmma::row_major> af[2];
            wmma::fragment<wmma::matrix_b, 16, 16, 8, wmma::precision::tf32, wmma::col_major> bf[2];
#pragma unroll
            for (int fy = 0; fy < 2; fy++) {
                wmma::load_matrix_sync(af[fy], As + (wy * 32 + fy * 16) * 40 + kk, 40);
#pragma unroll
                for (int e = 0; e < af[fy].num_elements; e++)
                    af[fy].x[e] = wmma::__float_to_tf32(af[fy].x[e]);
            }
#pragma unroll
            for (int fx = 0; fx < 2; fx++) {
                wmma::load_matrix_sync(bf[fx], Bs + (wx * 32 + fx * 16) * 40 + kk, 40);
#pragma unroll
                for (int e = 0; e < bf[fx].num_elements; e++)
                    bf[fx].x[e] = wmma::__float_to_tf32(bf[fx].x[e]);
            }
#pragma unroll
            for (int fy = 0; fy < 2; fy++)
#pragma unroll
                for (int fx = 0; fx < 2; fx++)
                    wmma::mma_sync(acc[fy][fx], af[fy], bf[fx], acc[fy][fx]);
        }
        __syncthreads();
    }

    float* Cs = smem;
#pragma unroll
    for (int fy = 0; fy < 2; fy++)
#pragma unroll
        for (int fx = 0; fx < 2; fx++)
            wmma::store_matrix_sync(Cs + (wy * 32 + fy * 16) * 68 + wx * 32 + fx * 16,
                                    acc[fy][fx], 68, wmma::mem_row_major);
    __syncthreads();
#pragma unroll
    for (int it = 0; it < 8; it++) {
        int idx = tid + it * 256;
        int r = idx >> 4, c4 = (idx & 15) << 2;
        int gi = i0 + r;
        if (gi >= M) continue;
        float4 v = *(float4*)(Cs + r * 68 + c4);
        if (bias) {
            v.x += bias[n0 + c4];     v.y += bias[n0 + c4 + 1];
            v.z += bias[n0 + c4 + 2]; v.w += bias[n0 + c4 + 3];
        }
        *(float4*)(C + (size_t)gi * ldc + n0 + c4) = v;
    }
}

// ---------------- fused intra GRU (xw interleaved) ----------------
__global__ void __launch_bounds__(768) intra_gru(
    const float* __restrict__ xw_intra,
    const float* __restrict__ w_hh,
    const float* __restrict__ b_ih, const float* __restrict__ b_hh,
    float* __restrict__ intra_h)
{
    int b = blockIdx.x;
    int tid = threadIdx.x;
    __shared__ float h_sh[256];
    __shared__ float gh_sh[768];
    if (tid < 256) h_sh[tid] = 0.f;
    __syncthreads();
    const float4* w4 = (const float4*)(w_hh + (size_t)tid * 256);
    for (int t = 0; t < Ss; t++) {
        float acc = 0.f;
        const float4* h4 = (const float4*)h_sh;
#pragma unroll 16
        for (int k = 0; k < 64; k++) {
            float4 w = w4[k];
            float4 h = h4[k];
            acc += w.x * h.x + w.y * h.y + w.z * h.z + w.w * h.w;
        }
        gh_sh[tid] = acc;
        __syncthreads();
        if (tid < 256) {
            const float* xwrow = xw_intra + ((size_t)b * Ss + t) * 768;
            float r = sigmoidf_(xwrow[3 * tid] + b_ih[tid] + gh_sh[tid] + b_hh[tid]);
            float z = sigmoidf_(xwrow[3 * tid + 1] + b_ih[256 + tid] + gh_sh[256 + tid] + b_hh[256 + tid]);
            float n = tanhf(xwrow[3 * tid + 2] + b_ih[512 + tid] + r * (gh_sh[512 + tid] + b_hh[512 + tid]));
            float hn = (1.f - z) * n + z * h_sh[tid];
            h_sh[tid] = hn;
            intra_h[((size_t)b * Ss + t) * 256 + tid] = hn;
        }
        __syncthreads();
    }
}

// ---------------- builders ----------------
__global__ void build_mrv(const float* __restrict__ inter_r,
                          const float* __restrict__ his_last, float* __restrict__ Mrv) {
    int idx = blockIdx.x * blockDim.x + threadIdx.x;
    if (idx >= NSEQ * 384) return;
    int i = idx / 384, c = idx % 384;
    Mrv[idx] = (c < 256) ? his_last[i * 256 + c] : inter_r[i * 128 + (c - 256)];
}

__global__ void build_mpv(const float* __restrict__ intra_x,
                          const float* __restrict__ intra_h, float* __restrict__ mpv) {
    int idx = blockIdx.x * blockDim.x + threadIdx.x;
    if (idx >= BS * 384) return;
    int i = idx / 384, c = idx % 384;
    float v;
    if (c < 256) v = intra_h[i * 256 + c];
    else if (c < 383) v = intra_x[i * 128 + (c - 256)];
    else v = 0.f;
    mpv[idx] = v;
}

__global__ void build_hp(const float* __restrict__ intra_x,
                         const float* __restrict__ intra_h, float* __restrict__ hp) {
    int idx = blockIdx.x * blockDim.x + threadIdx.x;
    if (idx >= BS * 257) return;
    int i = idx / 257, c = idx % 257;
    hp[i * 288 + c] = (c < 256) ? intra_h[i * 256 + c] : intra_x[i * 128 + 127];
}

__global__ void build_feat(const float* __restrict__ intra_x, const float* __restrict__ wr,
                           const float* __restrict__ vv, const float* __restrict__ vh,
                           const float* __restrict__ intra_h, float* __restrict__ feat) {
    int idx = blockIdx.x * blockDim.x + threadIdx.x;
    if (idx >= BS * 640) return;
    float e0 = expf(wr[0]), e1 = expf(wr[1]);
    float w0 = e0 / (e0 + e1), w1 = 1.f - w0;
    int i = idx / 640, c = idx % 640;
    float v;
    if (c < 256) v = w0 * vv[i * 256 + c] + w1 * vh[i * 256 + c];
    else if (c < 512) v = intra_h[i * 256 + (c - 256)];
    else if (c < 639) v = intra_x[i * 128 + (c - 512)];
    else v = 0.f;
    feat[idx] = v;
}

// ---------------- attention cores ----------------
__global__ void inter_attn(const float* __restrict__ qi, const float* __restrict__ ki,
                           const float* __restrict__ vi, float* __restrict__ oi) {
    int i = blockIdx.x;
    int tid = threadIdx.x;
    __shared__ float p[12];
    if (tid < 12) {
        int h = tid / 6, rr = tid % 6;
        const float* qp = qi + i * 256 + h * 128;
        const float* kp = ki + (i * 6 + rr) * 256 + h * 128;
        float acc = 0.f;
        for (int d = 0; d < 128; d++) acc += qp[d] * kp[d];
        p[tid] = acc * 0.08838834764831843f;
    }
    __syncthreads();
    if (tid < 2) {
        float mx = -1e30f;
        for (int r = 0; r < 6; r++) mx = fmaxf(mx, p[tid * 6 + r]);
        float sum = 0.f;
        for (int r = 0; r < 6; r++) { float e = expf(p[tid * 6 + r] - mx); p[tid * 6 + r] = e; sum += e; }
        float inv = 1.f / sum;
        for (int r = 0; r < 6; r++) p[tid * 6 + r] *= inv;
    }
    __syncthreads();
    for (int dd = tid; dd < 256; dd += 128) {
        int h = dd >> 7;
        float acc = 0.f;
        for (int r = 0; r < 6; r++) acc += p[h * 6 + r] * vi[(i * 6 + r) * 256 + dd];
        oi[i * 256 + dd] = acc;
    }
}

__global__ void intra_attn(const float* __restrict__ qh, const float* __restrict__ kh,
                           const float* __restrict__ vhp, float* __restrict__ oh) {
    int tq = blockIdx.x, head = blockIdx.y, b = blockIdx.z;
    int tid = threadIdx.x;
    __shared__ float p[64];
    __shared__ float invsum;
    const float* qp = qh + (b * 64 + tq) * 256 + head * 128;
    if (tid < 64) {
        float s = 0.f;
        if (tid <= tq) {
            const float* kp = kh + (b * 64 + tid) * 256 + head * 128;
            float acc = 0.f;
            for (int d = 0; d < 128; d++) acc += qp[d] * kp[d];
            s = acc * 0.08838834764831843f;
        }
        p[tid] = s;
    }
    __syncthreads();
    if (tid == 0) {
        float mx = -1e30f;
        for (int k = 0; k <= tq; k++) mx = fmaxf(mx, p[k]);
        float sum = 0.f;
        for (int k = 0; k <= tq; k++) { float e = expf(p[k] - mx); p[k] = e; sum += e; }
        invsum = 1.f / sum;
    }
    __syncthreads();
    float inv = invsum;
    {
        int d = tid;
        float acc = 0.f;
        for (int k = 0; k <= tq; k++) acc += p[k] * vhp[(b * 64 + k) * 256 + head * 128 + d];
        oh[(b * 64 + tq) * 256 + head * 128 + d] = acc * inv;
    }
}

// ---------------- launch ----------------
extern "C" void kernel_launch(void* const* d_in, const int* in_sizes, int n_in,
                              void* d_out, int out_size) {
    const float* intra_x   = (const float*)d_in[0];
    const float* inter_his = (const float*)d_in[1];
    const float* inter_r   = (const float*)d_in[2];
    const int*   inter_len = (const int*)d_in[4];
    const float* w_ih = (const float*)d_in[5];
    const float* w_hh = (const float*)d_in[6];
    const float* b_ih = (const float*)d_in[7];
    const float* b_hh = (const float*)d_in[8];
    const float* iq_w = (const float*)d_in[9];
    const float* iq_b = (const float*)d_in[10];
    const float* ik_w = (const float*)d_in[11];
    const float* ik_b = (const float*)d_in[12];
    const float* iv_w = (const float*)d_in[13];
    const float* iv_b = (const float*)d_in[14];
    const float* io_w = (const float*)d_in[15];
    const float* io_b = (const float*)d_in[16];
    const float* aq_w = (const float*)d_in[17];
    const float* aq_b = (const float*)d_in[18];
    const float* ak_w = (const float*)d_in[19];
    const float* ak_b = (const float*)d_in[20];
    const float* av_w = (const float*)d_in[21];
    const float* av_b = (const float*)d_in[22];
    const float* ao_w = (const float*)d_in[23];
    const float* ao_b = (const float*)d_in[24];
    const float* wr   = (const float*)d_in[25];
    const float* ln_w = (const float*)d_in[26];
    const float* ln_b = (const float*)d_in[27];
    float* out = (float*)d_out;

    float *p_Whh_i, *p_Wih_i, *p_bias_i, *p_xw, *p_xw_intra, *p_hA, *p_hB, *p_his, *p_ih;
    float *p_Mrv, *p_mpv, *p_hp, *p_qi, *p_ki, *p_vi, *p_oi, *p_vv, *p_qh, *p_kh, *p_vhp;
    float *p_oh, *p_vh, *p_feat, *p_Wq, *p_Wk, *p_Waq, *p_Wak, *p_Wav, *p_Wln;
    cudaGetSymbolAddress((void**)&p_Whh_i, g_Whh_i);
    cudaGetSymbolAddress((void**)&p_Wih_i, g_Wih_i);
    cudaGetSymbolAddress((void**)&p_bias_i, g_bias_i);
    cudaGetSymbolAddress((void**)&p_xw, g_xw_inter);
    cudaGetSymbolAddress((void**)&p_xw_intra, g_xw_intra);
    cudaGetSymbolAddress((void**)&p_hA, g_hA);
    cudaGetSymbolAddress((void**)&p_hB, g_hB);
    cudaGetSymbolAddress((void**)&p_his, g_his_last);
    cudaGetSymbolAddress((void**)&p_ih, g_intra_h);
    cudaGetSymbolAddress((void**)&p_Mrv, g_Mrv);
    cudaGetSymbolAddress((void**)&p_mpv, g_mpv);
    cudaGetSymbolAddress((void**)&p_hp, g_hp);
    cudaGetSymbolAddress((void**)&p_qi, g_qi);
    cudaGetSymbolAddress((void**)&p_ki, g_ki);
    cudaGetSymbolAddress((void**)&p_vi, g_vi);
    cudaGetSymbolAddress((void**)&p_oi, g_oi);
    cudaGetSymbolAddress((void**)&p_vv, g_vv);
    cudaGetSymbolAddress((void**)&p_qh, g_qh);
    cudaGetSymbolAddress((void**)&p_kh, g_kh);
    cudaGetSymbolAddress((void**)&p_vhp, g_vhp);
    cudaGetSymbolAddress((void**)&p_oh, g_oh);
    cudaGetSymbolAddress((void**)&p_vh, g_vh);
    cudaGetSymbolAddress((void**)&p_feat, g_feat);
    cudaGetSymbolAddress((void**)&p_Wq, g_Wq);
    cudaGetSymbolAddress((void**)&p_Wk, g_Wk);
    cudaGetSymbolAddress((void**)&p_Waq, g_Waq);
    cudaGetSymbolAddress((void**)&p_Wak, g_Wak);
    cudaGetSymbolAddress((void**)&p_Wav, g_Wav);
    cudaGetSymbolAddress((void**)&p_Wln, g_Wln);

    // [0-2] weight interleave
    prep_whh_i<<<(768 * 256 + 255) / 256, 256>>>(w_hh, p_Whh_i);
    prep_wih_i<<<(768 * 128 + 255) / 256, 256>>>(w_ih, p_Wih_i);
    prep_bias_i<<<3, 256>>>(b_ih, b_hh, p_bias_i);

    // [3] hoisted inter input projection (interleaved output)
    gemm_tc_wide<<<dim3(NROWS_XW / 64, 4), 256>>>(NROWS_XW, 128, inter_his, 128,
                                                  p_Wih_i, 128, p_xw, 768);

    // [4..27] inter GRU: 24 fused recurrent-GEMM + gate steps
    for (int t = 0; t < Ll; t++) {
        float* h_out  = (t & 1) ? p_hB : p_hA;
        float* h_prev = (t & 1) ? p_hA : p_hB;
        gru_fused_step<<<dim3(96, 4), 256>>>(t, p_Whh_i, p_xw, p_bias_i,
                                             inter_len, h_prev, h_out, p_his);
    }

    // intra path
    gemm_tc_wide<<<dim3(16, 4), 256>>>(BS, 128, intra_x, 128, p_Wih_i, 128, p_xw_intra, 768);
    intra_gru<<<Bb, 768>>>(p_xw_intra, w_hh, b_ih, b_hh, p_ih);

    // weight padding for MHA
    pad_w<<<(256 * 384 + 255) / 256, 256>>>(iq_w, p_Wq, 256, 383, 384);
    pad_w<<<(256 * 384 + 255) / 256, 256>>>(ik_w, p_Wk, 256, 383, 384);
    pad_w<<<(256 * 128 + 255) / 256, 256>>>(aq_w, p_Waq, 256, 127, 128);
    pad_w<<<(256 * 128 + 255) / 256, 256>>>(ak_w, p_Wak, 256, 127, 128);
    pad_w<<<(256 * 288 + 255) / 256, 256>>>(av_w, p_Wav, 256, 257, 288);
    pad_w<<<(256 * 640 + 255) / 256, 256>>>(ln_w, p_Wln, 256, 639, 640);

    // builders
    build_mrv<<<(NSEQ * 384 + 255) / 256, 256>>>(inter_r, p_his, p_Mrv);
    build_mpv<<<(BS * 384 + 255) / 256, 256>>>(intra_x, p_ih, p_mpv);
    build_hp<<<(BS * 257 + 255) / 256, 256>>>(intra_x, p_ih, p_hp);

    // inter MHA
    gemm_tc<<<dim3(8, 4), 256>>>(BS, 256, 384, p_mpv, 384, p_Wq, 384, iq_b, p_qi, 256);
    gemm_tc<<<dim3(48, 4), 256>>>(NSEQ, 256, 384, p_Mrv, 384, p_Wk, 384, ik_b, p_ki, 256);
    gemm_tc<<<dim3(48, 4), 256>>>(NSEQ, 256, 384, p_Mrv, 384, iv_w, 384, iv_b, p_vi, 256);
    inter_attn<<<BS, 128>>>(p_qi, p_ki, p_vi, p_oi);
    gemm_tc<<<dim3(8, 4), 256>>>(BS, 256, 256, p_oi, 256, io_w, 256, io_b, p_vv, 256);

    // intra MHA
    gemm_tc<<<dim3(8, 4), 256>>>(BS, 256, 128, intra_x, 128, p_Waq, 128, aq_b, p_qh, 256);
    gemm_tc<<<dim3(8, 4), 256>>>(BS, 256, 128, intra_x, 128, p_Wak, 128, ak_b, p_kh, 256);
    gemm_tc<<<dim3(8, 4), 256>>>(BS, 256, 288, p_hp, 288, p_Wav, 288, av_b, p_vhp, 256);
    intra_attn<<<dim3(64, 2, 16), 128>>>(p_qh, p_kh, p_vhp, p_oh);
    gemm_tc<<<dim3(8, 4), 256>>>(BS, 256, 256, p_oh, 256, ao_w, 256, ao_b, p_vh, 256);

    // combine + final projection
    build_feat<<<(BS * 640 + 255) / 256, 256>>>(intra_x, wr, p_vv, p_vh, p_ih, p_feat);
    gemm_tc<<<dim3(8, 4), 256>>>(BS, 256, 640, p_feat, 640, p_Wln, 640, ln_b, out, 256);
}

// round 6
// speedup vs baseline: 1.1694x; 1.1694x over previous
#include <cuda_runtime.h>
#include <mma.h>
#include <math.h>
using namespace nvcuda;

// Problem dims
#define Bb 16
#define Ss 64
#define Rr 6
#define Ll 24
#define Dd 128
#define Hh 256
#define BS 1024      // B*S
#define NSEQ 6144    // B*S*R
#define NROWS_XW (NSEQ * Ll)   // 147456

// ---------------- scratch (device globals; no allocations allowed) ----------------
__device__ float g_Whh_i[768 * 256];     // interleaved: row 3j+g = w_hh[g*256+j]
__device__ float g_Wih_i[768 * 128];     // interleaved: row 3j+g = w_ih[g*256+j]
__device__ float g_bias_i[2 * 768];
__device__ float g_xw_inter[(size_t)NROWS_XW * 768];
__device__ float g_xw_intra[BS * 768];
__device__ float g_hA[NSEQ * Hh];
__device__ float g_hB[NSEQ * Hh];
__device__ float g_his_last[NSEQ * Hh];
__device__ float g_intra_h[BS * Hh];
__device__ float g_Mrv[NSEQ * 384];
__device__ float g_mpv[BS * 384];
__device__ float g_hp[BS * 288];
__device__ float g_qi[BS * Hh];
__device__ float g_ki[NSEQ * Hh];
__device__ float g_vi[NSEQ * Hh];
__device__ float g_oi[BS * Hh];
__device__ float g_vv[BS * Hh];
__device__ float g_qh[BS * Hh];
__device__ float g_kh[BS * Hh];
__device__ float g_vhp[BS * Hh];
__device__ float g_oh[BS * Hh];
__device__ float g_vh[BS * Hh];
__device__ float g_feat[BS * 640];
__device__ float g_Wq[256 * 384];
__device__ float g_Wk[256 * 384];
__device__ float g_Waq[256 * 128];
__device__ float g_Wak[256 * 128];
__device__ float g_Wav[256 * 288];
__device__ float g_Wln[256 * 640];

__device__ __forceinline__ float sigmoidf_(float x) { return 1.f / (1.f + expf(-x)); }
__device__ __forceinline__ float4 tf32_4(float4 v) {
    v.x = wmma::__float_to_tf32(v.x);
    v.y = wmma::__float_to_tf32(v.y);
    v.z = wmma::__float_to_tf32(v.z);
    v.w = wmma::__float_to_tf32(v.w);
    return v;
}

// ---------------- weight interleaving / padding ----------------
__global__ void prep_whh_i(const float* __restrict__ w_hh, float* __restrict__ dst) {
    int idx = blockIdx.x * blockDim.x + threadIdx.x;
    if (idx >= 768 * 256) return;
    int row = idx >> 8, k = idx & 255;
    int j = row / 3, g = row % 3;
    dst[idx] = w_hh[(g * 256 + j) * 256 + k];
}
__global__ void prep_wih_i(const float* __restrict__ w_ih, float* __restrict__ dst) {
    int idx = blockIdx.x * blockDim.x + threadIdx.x;
    if (idx >= 768 * 128) return;
    int row = idx >> 7, k = idx & 127;
    int j = row / 3, g = row % 3;
    dst[idx] = w_ih[(g * 256 + j) * 128 + k];
}
__global__ void prep_bias_i(const float* __restrict__ b_ih, const float* __restrict__ b_hh,
                            float* __restrict__ dst) {
    int idx = blockIdx.x * blockDim.x + threadIdx.x;
    if (idx >= 768) return;
    int j = idx / 3, g = idx % 3;
    dst[idx] = b_ih[g * 256 + j];
    dst[768 + idx] = b_hh[g * 256 + j];
}
__global__ void pad_w(const float* __restrict__ src, float* __restrict__ dst,
                      int N, int Ks, int Kd) {
    int idx = blockIdx.x * blockDim.x + threadIdx.x;
    if (idx >= N * Kd) return;
    int n = idx / Kd, k = idx % Kd;
    dst[idx] = (k < Ks) ? src[n * Ks + k] : 0.f;
}

// ---------------- wide tf32 GEMM: tile 64x192, prefetch-pipelined, 2 blocks/SM -----
__global__ void __launch_bounds__(256, 2) gemm_tc_wide(
    int M, int K,
    const float* __restrict__ A, int lda,
    const float* __restrict__ W, int ldw,
    float* __restrict__ C, int ldc)
{
    __shared__ float smem[64 * 36 + 192 * 36];
    float* As = smem;                 // [64][36]
    float* Bs = smem + 64 * 36;       // [192][36]
    float* Cs = smem;                 // [32][196] per pass

    int i0 = blockIdx.x * 64, n0 = blockIdx.y * 192;
    int tid = threadIdx.x;
    int warp = tid >> 5, wy = warp >> 2, wx = warp & 3;

    wmma::fragment<wmma::accumulator, 16, 16, 8, float> acc[2][3];
#pragma unroll
    for (int a = 0; a < 2; a++)
#pragma unroll
        for (int b = 0; b < 3; b++) wmma::fill_fragment(acc[a][b], 0.f);

    float4 ra[2], rb[6];
    auto ldchunk = [&](int k0) {
#pragma unroll
        for (int it = 0; it < 2; it++) {
            int idx = tid + it * 256;
            int r = idx >> 3, k4 = (idx & 7) << 2;
            float4 v = make_float4(0.f, 0.f, 0.f, 0.f);
            if (i0 + r < M) v = *(const float4*)(A + (size_t)(i0 + r) * lda + k0 + k4);
            ra[it] = v;
        }
#pragma unroll
        for (int it = 0; it < 6; it++) {
            int idx = tid + it * 256;
            int c = idx >> 3, k4 = (idx & 7) << 2;
            rb[it] = *(const float4*)(W + (size_t)(n0 + c) * ldw + k0 + k4);
        }
    };
    auto stchunk = [&]() {
#pragma unroll
        for (int it = 0; it < 2; it++) {
            int idx = tid + it * 256;
            int r = idx >> 3, k4 = (idx & 7) << 2;
            *(float4*)(As + r * 36 + k4) = tf32_4(ra[it]);
        }
#pragma unroll
        for (int it = 0; it < 6; it++) {
            int idx = tid + it * 256;
            int c = idx >> 3, k4 = (idx & 7) << 2;
            *(float4*)(Bs + c * 36 + k4) = tf32_4(rb[it]);
        }
    };

    ldchunk(0); stchunk(); __syncthreads();
    for (int k0 = 0; k0 < K; k0 += 32) {
        bool more = (k0 + 32) < K;
        if (more) ldchunk(k0 + 32);
#pragma unroll
        for (int kk = 0; kk < 32; kk += 8) {
            wmma::fragment<wmma::matrix_a, 16, 16, 8, wmma::precision::tf32, wmma::row_major> af[2];
            wmma::fragment<wmma::matrix_b, 16, 16, 8, wmma::precision::tf32, wmma::col_major> bf[3];
#pragma unroll
            for (int fy = 0; fy < 2; fy++)
                wmma::load_matrix_sync(af[fy], As + (wy * 32 + fy * 16) * 36 + kk, 36);
#pragma unroll
            for (int fx = 0; fx < 3; fx++)
                wmma::load_matrix_sync(bf[fx], Bs + (wx * 48 + fx * 16) * 36 + kk, 36);
#pragma unroll
            for (int fy = 0; fy < 2; fy++)
#pragma unroll
                for (int fx = 0; fx < 3; fx++)
                    wmma::mma_sync(acc[fy][fx], af[fy], bf[fx], acc[fy][fx]);
        }
        __syncthreads();
        if (more) { stchunk(); __syncthreads(); }
    }

    for (int pass = 0; pass < 2; pass++) {
        __syncthreads();
        if (wy == pass) {
#pragma unroll
            for (int fy = 0; fy < 2; fy++)
#pragma unroll
                for (int fx = 0; fx < 3; fx++)
                    wmma::store_matrix_sync(Cs + (fy * 16) * 196 + wx * 48 + fx * 16,
                                            acc[fy][fx], 196, wmma::mem_row_major);
        }
        __syncthreads();
#pragma unroll
        for (int it = 0; it < 6; it++) {
            int idx = tid + it * 256;
            int row = idx / 48, c4 = (idx % 48) << 2;
            int gi = i0 + pass * 32 + row;
            if (gi >= M) continue;
            float4 v = *(float4*)(Cs + row * 196 + c4);
            *(float4*)(C + (size_t)gi * ldc + n0 + c4) = v;
        }
    }
}

// ---------------- fused recurrent GEMM + GRU gate, prefetch-pipelined --------------
__global__ void __launch_bounds__(256, 2) gru_fused_step(
    int t,
    const float* __restrict__ Whh_i,
    const float* __restrict__ xw,
    const float* __restrict__ bias_i,
    const int* __restrict__ lenp,
    const float* __restrict__ h_prev, float* __restrict__ h_out,
    float* __restrict__ his_last)
{
    __shared__ float smem[64 * 36 + 192 * 36];
    float* As = smem;
    float* Bs = smem + 64 * 36;
    float* Cs = smem;                // [32][196]

    const int i0 = blockIdx.x * 64;
    const int n0 = blockIdx.y * 192;
    const int tid = threadIdx.x;
    const int warp = tid >> 5, wy = warp >> 2, wx = warp & 3;

    wmma::fragment<wmma::accumulator, 16, 16, 8, float> acc[2][3];
#pragma unroll
    for (int a = 0; a < 2; a++)
#pragma unroll
        for (int b = 0; b < 3; b++) wmma::fill_fragment(acc[a][b], 0.f);

    if (t > 0) {
        float4 ra[2], rb[6];
        auto ldchunk = [&](int k0) {
#pragma unroll
            for (int it = 0; it < 2; it++) {
                int idx = tid + it * 256;
                int r = idx >> 3, k4 = (idx & 7) << 2;
                ra[it] = *(const float4*)(h_prev + (size_t)(i0 + r) * 256 + k0 + k4);
            }
#pragma unroll
            for (int it = 0; it < 6; it++) {
                int idx = tid + it * 256;
                int c = idx >> 3, k4 = (idx & 7) << 2;
                rb[it] = *(const float4*)(Whh_i + (size_t)(n0 + c) * 256 + k0 + k4);
            }
        };
        auto stchunk = [&]() {
#pragma unroll
            for (int it = 0; it < 2; it++) {
                int idx = tid + it * 256;
                int r = idx >> 3, k4 = (idx & 7) << 2;
                *(float4*)(As + r * 36 + k4) = tf32_4(ra[it]);
            }
#pragma unroll
            for (int it = 0; it < 6; it++) {
                int idx = tid + it * 256;
                int c = idx >> 3, k4 = (idx & 7) << 2;
                *(float4*)(Bs + c * 36 + k4) = tf32_4(rb[it]);
            }
        };

        ldchunk(0); stchunk(); __syncthreads();
        for (int k0 = 0; k0 < 256; k0 += 32) {
            bool more = (k0 + 32) < 256;
            if (more) ldchunk(k0 + 32);
#pragma unroll
            for (int kk = 0; kk < 32; kk += 8) {
                wmma::fragment<wmma::matrix_a, 16, 16, 8, wmma::precision::tf32, wmma::row_major> af[2];
                wmma::fragment<wmma::matrix_b, 16, 16, 8, wmma::precision::tf32, wmma::col_major> bf[3];
#pragma unroll
                for (int fy = 0; fy < 2; fy++)
                    wmma::load_matrix_sync(af[fy], As + (wy * 32 + fy * 16) * 36 + kk, 36);
#pragma unroll
                for (int fx = 0; fx < 3; fx++)
                    wmma::load_matrix_sync(bf[fx], Bs + (wx * 48 + fx * 16) * 36 + kk, 36);
#pragma unroll
                for (int fy = 0; fy < 2; fy++)
#pragma unroll
                    for (int fx = 0; fx < 3; fx++)
                        wmma::mma_sync(acc[fy][fx], af[fy], bf[fx], acc[fy][fx]);
            }
            __syncthreads();
            if (more) { stchunk(); __syncthreads(); }
        }
    }

    // ---- gate epilogue, two 32-row passes
    for (int pass = 0; pass < 2; pass++) {
        __syncthreads();
        if (wy == pass) {
#pragma unroll
            for (int fy = 0; fy < 2; fy++)
#pragma unroll
                for (int fx = 0; fx < 3; fx++)
                    wmma::store_matrix_sync(Cs + (fy * 16) * 196 + wx * 48 + fx * 16,
                                            acc[fy][fx], 196, wmma::mem_row_major);
        }
        __syncthreads();
#pragma unroll
        for (int it = 0; it < 8; it++) {
            int idx = tid + it * 256;      // 2048 = 32 rows x 64 units
            int row = idx >> 6, jl = idx & 63;
            int gi = i0 + pass * 32 + row;
            int c = 3 * jl;
            int j = (n0 / 3) + jl;
            float ghr = Cs[row * 196 + c];
            float ghz = Cs[row * 196 + c + 1];
            float ghn = Cs[row * 196 + c + 2];
            const float* xwrow = xw + ((size_t)gi * Ll + t) * 768 + n0 + c;
            float xr = xwrow[0], xz = xwrow[1], xn = xwrow[2];
            float bir = bias_i[n0 + c],       biz = bias_i[n0 + c + 1],       bin = bias_i[n0 + c + 2];
            float bhr = bias_i[768 + n0 + c], bhz = bias_i[768 + n0 + c + 1], bhn = bias_i[768 + n0 + c + 2];
            float hp = (t > 0) ? h_prev[(size_t)gi * 256 + j] : 0.f;
            float r = sigmoidf_(xr + bir + ghr + bhr);
            float z = sigmoidf_(xz + biz + ghz + bhz);
            float n = tanhf(xn + bin + r * (ghn + bhn));
            float h = (1.f - z) * n + z * hp;
            h_out[(size_t)gi * 256 + j] = h;
            if (lenp[gi] == t + 1) his_last[(size_t)gi * 256 + j] = h;
        }
        __syncthreads();
    }
}

// ---------------- tf32 GEMM (tile 128x64): C = A @ W^T + bias, pipelined -----------
__global__ void __launch_bounds__(256, 2) gemm_tc(
    int M, int N, int K,
    const float* __restrict__ A, int lda,
    const float* __restrict__ W, int ldw,
    const float* __restrict__ bias,
    float* __restrict__ C, int ldc)
{
    __shared__ float smem[128 * 68];
    float* As = smem;
    float* Bs = smem + 128 * 40;

    int i0 = blockIdx.x * 128, n0 = blockIdx.y * 64;
    int tid = threadIdx.x;
    int warp = tid >> 5;
    int wy = warp >> 1, wx = warp & 1;

    wmma::fragment<wmma::accumulator, 16, 16, 8, float> acc[2][2];
#pragma unroll
    for (int a = 0; a < 2; a++)
#pragma unroll
        for (int b = 0; b < 2; b++) wmma::fill_fragment(acc[a][b], 0.f);

    float4 ra[4], rb[2];
    auto ldchunk = [&](int k0) {
#pragma unroll
        for (int it = 0; it < 4; it++) {
            int idx = tid + it * 256;
            int r = idx >> 3, k4 = (idx & 7) << 2;
            float4 v = make_float4(0.f, 0.f, 0.f, 0.f);
            int gi = i0 + r;
            if (gi < M) v = *(const float4*)(A + (size_t)gi * lda + k0 + k4);
            ra[it] = v;
        }
#pragma unroll
        for (int it = 0; it < 2; it++) {
            int idx = tid + it * 256;
            int n = idx >> 3, k4 = (idx & 7) << 2;
            rb[it] = *(const float4*)(W + (size_t)(n0 + n) * ldw + k0 + k4);
        }
    };
    auto stchunk = [&]() {
#pragma unroll
        for (int it = 0; it < 4; it++) {
            int idx = tid + it * 256;
            int r = idx >> 3, k4 = (idx & 7) << 2;
            *(float4*)(As + r * 40 + k4) = tf32_4(ra[it]);
        }
#pragma unroll
        for (int it = 0; it < 2; it++) {
            int idx = tid + it * 256;
            int n = idx >> 3, k4 = (idx & 7) << 2;
            *(float4*)(Bs + n * 40 + k4) = tf32_4(rb[it]);
        }
    };

    ldchunk(0); stchunk(); __syncthreads();
    for (int k0 = 0; k0 < K; k0 += 32) {
        bool more = (k0 + 32) < K;
        if (more) ldchunk(k0 + 32);
#pragma unroll
        for (int kk = 0; kk < 32; kk += 8) {
            wmma::fragment<wmma::matrix_a, 16, 16, 8, wmma::precision::tf32, wmma::row_major> af[2];
            wmma::fragment<wmma::matrix_b, 16, 16, 8, wmma::precision::tf32, wmma::col_major> bf[2];
#pragma unroll
            for (int fy = 0; fy < 2; fy++)
                wmma::load_matrix_sync(af[fy], As + (wy * 32 + fy * 16) * 40 + kk, 40);
#pragma unroll
            for (int fx = 0; fx < 2; fx++)
                wmma::load_matrix_sync(bf[fx], Bs + (wx * 32 + fx * 16) * 40 + kk, 40);
#pragma unroll
            for (int fy = 0; fy < 2; fy++)
#pragma unroll
                for (int fx = 0; fx < 2; fx++)
                    wmma::mma_sync(acc[fy][fx], af[fy], bf[fx], acc[fy][fx]);
        }
        __syncthreads();
        if (more) { stchunk(); __syncthreads(); }
    }

    float* Cs = smem;
#pragma unroll
    for (int fy = 0; fy < 2; fy++)
#pragma unroll
        for (int fx = 0; fx < 2; fx++)
            wmma::store_matrix_sync(Cs + (wy * 32 + fy * 16) * 68 + wx * 32 + fx * 16,
                                    acc[fy][fx], 68, wmma::mem_row_major);
    __syncthreads();
#pragma unroll
    for (int it = 0; it < 8; it++) {
        int idx = tid + it * 256;
        int r = idx >> 4, c4 = (idx & 15) << 2;
        int gi = i0 + r;
        if (gi >= M) continue;
        float4 v = *(float4*)(Cs + r * 68 + c4);
        if (bias) {
            v.x += bias[n0 + c4];     v.y += bias[n0 + c4 + 1];
            v.z += bias[n0 + c4 + 2]; v.w += bias[n0 + c4 + 3];
        }
        *(float4*)(C + (size_t)gi * ldc + n0 + c4) = v;
    }
}

// ---------------- fused intra GRU (xw interleaved) ----------------
__global__ void __launch_bounds__(768) intra_gru(
    const float* __restrict__ xw_intra,
    const float* __restrict__ w_hh,
    const float* __restrict__ b_ih, const float* __restrict__ b_hh,
    float* __restrict__ intra_h)
{
    int b = blockIdx.x;
    int tid = threadIdx.x;
    __shared__ float h_sh[256];
    __shared__ float gh_sh[768];
    if (tid < 256) h_sh[tid] = 0.f;
    __syncthreads();
    const float4* w4 = (const float4*)(w_hh + (size_t)tid * 256);
    for (int t = 0; t < Ss; t++) {
        float acc = 0.f;
        const float4* h4 = (const float4*)h_sh;
#pragma unroll 16
        for (int k = 0; k < 64; k++) {
            float4 w = w4[k];
            float4 h = h4[k];
            acc += w.x * h.x + w.y * h.y + w.z * h.z + w.w * h.w;
        }
        gh_sh[tid] = acc;
        __syncthreads();
        if (tid < 256) {
            const float* xwrow = xw_intra + ((size_t)b * Ss + t) * 768;
            float r = sigmoidf_(xwrow[3 * tid] + b_ih[tid] + gh_sh[tid] + b_hh[tid]);
            float z = sigmoidf_(xwrow[3 * tid + 1] + b_ih[256 + tid] + gh_sh[256 + tid] + b_hh[256 + tid]);
            float n = tanhf(xwrow[3 * tid + 2] + b_ih[512 + tid] + r * (gh_sh[512 + tid] + b_hh[512 + tid]));
            float hn = (1.f - z) * n + z * h_sh[tid];
            h_sh[tid] = hn;
            intra_h[((size_t)b * Ss + t) * 256 + tid] = hn;
        }
        __syncthreads();
    }
}

// ---------------- builders ----------------
__global__ void build_mrv(const float* __restrict__ inter_r,
                          const float* __restrict__ his_last, float* __restrict__ Mrv) {
    int idx = blockIdx.x * blockDim.x + threadIdx.x;
    if (idx >= NSEQ * 384) return;
    int i = idx / 384, c = idx % 384;
    Mrv[idx] = (c < 256) ? his_last[i * 256 + c] : inter_r[i * 128 + (c - 256)];
}

__global__ void build_mpv(const float* __restrict__ intra_x,
                          const float* __restrict__ intra_h, float* __restrict__ mpv) {
    int idx = blockIdx.x * blockDim.x + threadIdx.x;
    if (idx >= BS * 384) return;
    int i = idx / 384, c = idx % 384;
    float v;
    if (c < 256) v = intra_h[i * 256 + c];
    else if (c < 383) v = intra_x[i * 128 + (c - 256)];
    else v = 0.f;
    mpv[idx] = v;
}

__global__ void build_hp(const float* __restrict__ intra_x,
                         const float* __restrict__ intra_h, float* __restrict__ hp) {
    int idx = blockIdx.x * blockDim.x + threadIdx.x;
    if (idx >= BS * 257) return;
    int i = idx / 257, c = idx % 257;
    hp[i * 288 + c] = (c < 256) ? intra_h[i * 256 + c] : intra_x[i * 128 + 127];
}

__global__ void build_feat(const float* __restrict__ intra_x, const float* __restrict__ wr,
                           const float* __restrict__ vv, const float* __restrict__ vh,
                           const float* __restrict__ intra_h, float* __restrict__ feat) {
    int idx = blockIdx.x * blockDim.x + threadIdx.x;
    if (idx >= BS * 640) return;
    float e0 = expf(wr[0]), e1 = expf(wr[1]);
    float w0 = e0 / (e0 + e1), w1 = 1.f - w0;
    int i = idx / 640, c = idx % 640;
    float v;
    if (c < 256) v = w0 * vv[i * 256 + c] + w1 * vh[i * 256 + c];
    else if (c < 512) v = intra_h[i * 256 + (c - 256)];
    else if (c < 639) v = intra_x[i * 128 + (c - 512)];
    else v = 0.f;
    feat[idx] = v;
}

// ---------------- attention cores ----------------
__global__ void inter_attn(const float* __restrict__ qi, const float* __restrict__ ki,
                           const float* __restrict__ vi, float* __restrict__ oi) {
    int i = blockIdx.x;
    int tid = threadIdx.x;
    __shared__ float p[12];
    if (tid < 12) {
        int h = tid / 6, rr = tid % 6;
        const float* qp = qi + i * 256 + h * 128;
        const float* kp = ki + (i * 6 + rr) * 256 + h * 128;
        float acc = 0.f;
        for (int d = 0; d < 128; d++) acc += qp[d] * kp[d];
        p[tid] = acc * 0.08838834764831843f;
    }
    __syncthreads();
    if (tid < 2) {
        float mx = -1e30f;
        for (int r = 0; r < 6; r++) mx = fmaxf(mx, p[tid * 6 + r]);
        float sum = 0.f;
        for (int r = 0; r < 6; r++) { float e = expf(p[tid * 6 + r] - mx); p[tid * 6 + r] = e; sum += e; }
        float inv = 1.f / sum;
        for (int r = 0; r < 6; r++) p[tid * 6 + r] *= inv;
    }
    __syncthreads();
    for (int dd = tid; dd < 256; dd += 128) {
        int h = dd >> 7;
        float acc = 0.f;
        for (int r = 0; r < 6; r++) acc += p[h * 6 + r] * vi[(i * 6 + r) * 256 + dd];
        oi[i * 256 + dd] = acc;
    }
}

__global__ void intra_attn(const float* __restrict__ qh, const float* __restrict__ kh,
                           const float* __restrict__ vhp, float* __restrict__ oh) {
    int tq = blockIdx.x, head = blockIdx.y, b = blockIdx.z;
    int tid = threadIdx.x;
    __shared__ float p[64];
    __shared__ float invsum;
    const float* qp = qh + (b * 64 + tq) * 256 + head * 128;
    if (tid < 64) {
        float s = 0.f;
        if (tid <= tq) {
            const float* kp = kh + (b * 64 + tid) * 256 + head * 128;
            float acc = 0.f;
            for (int d = 0; d < 128; d++) acc += qp[d] * kp[d];
            s = acc * 0.08838834764831843f;
        }
        p[tid] = s;
    }
    __syncthreads();
    if (tid == 0) {
        float mx = -1e30f;
        for (int k = 0; k <= tq; k++) mx = fmaxf(mx, p[k]);
        float sum = 0.f;
        for (int k = 0; k <= tq; k++) { float e = expf(p[k] - mx); p[k] = e; sum += e; }
        invsum = 1.f / sum;
    }
    __syncthreads();
    float inv = invsum;
    {
        int d = tid;
        float acc = 0.f;
        for (int k = 0; k <= tq; k++) acc += p[k] * vhp[(b * 64 + k) * 256 + head * 128 + d];
        oh[(b * 64 + tq) * 256 + head * 128 + d] = acc * inv;
    }
}

// ---------------- launch ----------------
extern "C" void kernel_launch(void* const* d_in, const int* in_sizes, int n_in,
                              void* d_out, int out_size) {
    const float* intra_x   = (const float*)d_in[0];
    const float* inter_his = (const float*)d_in[1];
    const float* inter_r   = (const float*)d_in[2];
    const int*   inter_len = (const int*)d_in[4];
    const float* w_ih = (const float*)d_in[5];
    const float* w_hh = (const float*)d_in[6];
    const float* b_ih = (const float*)d_in[7];
    const float* b_hh = (const float*)d_in[8];
    const float* iq_w = (const float*)d_in[9];
    const float* iq_b = (const float*)d_in[10];
    const float* ik_w = (const float*)d_in[11];
    const float* ik_b = (const float*)d_in[12];
    const float* iv_w = (const float*)d_in[13];
    const float* iv_b = (const float*)d_in[14];
    const float* io_w = (const float*)d_in[15];
    const float* io_b = (const float*)d_in[16];
    const float* aq_w = (const float*)d_in[17];
    const float* aq_b = (const float*)d_in[18];
    const float* ak_w = (const float*)d_in[19];
    const float* ak_b = (const float*)d_in[20];
    const float* av_w = (const float*)d_in[21];
    const float* av_b = (const float*)d_in[22];
    const float* ao_w = (const float*)d_in[23];
    const float* ao_b = (const float*)d_in[24];
    const float* wr   = (const float*)d_in[25];
    const float* ln_w = (const float*)d_in[26];
    const float* ln_b = (const float*)d_in[27];
    float* out = (float*)d_out;

    float *p_Whh_i, *p_Wih_i, *p_bias_i, *p_xw, *p_xw_intra, *p_hA, *p_hB, *p_his, *p_ih;
    float *p_Mrv, *p_mpv, *p_hp, *p_qi, *p_ki, *p_vi, *p_oi, *p_vv, *p_qh, *p_kh, *p_vhp;
    float *p_oh, *p_vh, *p_feat, *p_Wq, *p_Wk, *p_Waq, *p_Wak, *p_Wav, *p_Wln;
    cudaGetSymbolAddress((void**)&p_Whh_i, g_Whh_i);
    cudaGetSymbolAddress((void**)&p_Wih_i, g_Wih_i);
    cudaGetSymbolAddress((void**)&p_bias_i, g_bias_i);
    cudaGetSymbolAddress((void**)&p_xw, g_xw_inter);
    cudaGetSymbolAddress((void**)&p_xw_intra, g_xw_intra);
    cudaGetSymbolAddress((void**)&p_hA, g_hA);
    cudaGetSymbolAddress((void**)&p_hB, g_hB);
    cudaGetSymbolAddress((void**)&p_his, g_his_last);
    cudaGetSymbolAddress((void**)&p_ih, g_intra_h);
    cudaGetSymbolAddress((void**)&p_Mrv, g_Mrv);
    cudaGetSymbolAddress((void**)&p_mpv, g_mpv);
    cudaGetSymbolAddress((void**)&p_hp, g_hp);
    cudaGetSymbolAddress((void**)&p_qi, g_qi);
    cudaGetSymbolAddress((void**)&p_ki, g_ki);
    cudaGetSymbolAddress((void**)&p_vi, g_vi);
    cudaGetSymbolAddress((void**)&p_oi, g_oi);
    cudaGetSymbolAddress((void**)&p_vv, g_vv);
    cudaGetSymbolAddress((void**)&p_qh, g_qh);
    cudaGetSymbolAddress((void**)&p_kh, g_kh);
    cudaGetSymbolAddress((void**)&p_vhp, g_vhp);
    cudaGetSymbolAddress((void**)&p_oh, g_oh);
    cudaGetSymbolAddress((void**)&p_vh, g_vh);
    cudaGetSymbolAddress((void**)&p_feat, g_feat);
    cudaGetSymbolAddress((void**)&p_Wq, g_Wq);
    cudaGetSymbolAddress((void**)&p_Wk, g_Wk);
    cudaGetSymbolAddress((void**)&p_Waq, g_Waq);
    cudaGetSymbolAddress((void**)&p_Wak, g_Wak);
    cudaGetSymbolAddress((void**)&p_Wav, g_Wav);
    cudaGetSymbolAddress((void**)&p_Wln, g_Wln);

    // [0-2] weight interleave
    prep_whh_i<<<(768 * 256 + 255) / 256, 256>>>(w_hh, p_Whh_i);
    prep_wih_i<<<(768 * 128 + 255) / 256, 256>>>(w_ih, p_Wih_i);
    prep_bias_i<<<3, 256>>>(b_ih, b_hh, p_bias_i);

    // [3] hoisted inter input projection (interleaved output)
    gemm_tc_wide<<<dim3(NROWS_XW / 64, 4), 256>>>(NROWS_XW, 128, inter_his, 128,
                                                  p_Wih_i, 128, p_xw, 768);

    // [4..27] inter GRU: 24 fused recurrent-GEMM + gate steps
    for (int t = 0; t < Ll; t++) {
        float* h_out  = (t & 1) ? p_hB : p_hA;
        float* h_prev = (t & 1) ? p_hA : p_hB;
        gru_fused_step<<<dim3(96, 4), 256>>>(t, p_Whh_i, p_xw, p_bias_i,
                                             inter_len, h_prev, h_out, p_his);
    }

    // intra path
    gemm_tc_wide<<<dim3(16, 4), 256>>>(BS, 128, intra_x, 128, p_Wih_i, 128, p_xw_intra, 768);
    intra_gru<<<Bb, 768>>>(p_xw_intra, w_hh, b_ih, b_hh, p_ih);

    // weight padding for MHA
    pad_w<<<(256 * 384 + 255) / 256, 256>>>(iq_w, p_Wq, 256, 383, 384);
    pad_w<<<(256 * 384 + 255) / 256, 256>>>(ik_w, p_Wk, 256, 383, 384);
    pad_w<<<(256 * 128 + 255) / 256, 256>>>(aq_w, p_Waq, 256, 127, 128);
    pad_w<<<(256 * 128 + 255) / 256, 256>>>(ak_w, p_Wak, 256, 127, 128);
    pad_w<<<(256 * 288 + 255) / 256, 256>>>(av_w, p_Wav, 256, 257, 288);
    pad_w<<<(256 * 640 + 255) / 256, 256>>>(ln_w, p_Wln, 256, 639, 640);

    // builders
    build_mrv<<<(NSEQ * 384 + 255) / 256, 256>>>(inter_r, p_his, p_Mrv);
    build_mpv<<<(BS * 384 + 255) / 256, 256>>>(intra_x, p_ih, p_mpv);
    build_hp<<<(BS * 257 + 255) / 256, 256>>>(intra_x, p_ih, p_hp);

    // inter MHA
    gemm_tc<<<dim3(8, 4), 256>>>(BS, 256, 384, p_mpv, 384, p_Wq, 384, iq_b, p_qi, 256);
    gemm_tc<<<dim3(48, 4), 256>>>(NSEQ, 256, 384, p_Mrv, 384, p_Wk, 384, ik_b, p_ki, 256);
    gemm_tc<<<dim3(48, 4), 256>>>(NSEQ, 256, 384, p_Mrv, 384, iv_w, 384, iv_b, p_vi, 256);
    inter_attn<<<BS, 128>>>(p_qi, p_ki, p_vi, p_oi);
    gemm_tc<<<dim3(8, 4), 256>>>(BS, 256, 256, p_oi, 256, io_w, 256, io_b, p_vv, 256);

    // intra MHA
    gemm_tc<<<dim3(8, 4), 256>>>(BS, 256, 128, intra_x, 128, p_Waq, 128, aq_b, p_qh, 256);
    gemm_tc<<<dim3(8, 4), 256>>>(BS, 256, 128, intra_x, 128, p_Wak, 128, ak_b, p_kh, 256);
    gemm_tc<<<dim3(8, 4), 256>>>(BS, 256, 288, p_hp, 288, p_Wav, 288, av_b, p_vhp, 256);
    intra_attn<<<dim3(64, 2, 16), 128>>>(p_qh, p_kh, p_vhp, p_oh);
    gemm_tc<<<dim3(8, 4), 256>>>(BS, 256, 256, p_oh, 256, ao_w, 256, ao_b, p_vh, 256);

    // combine + final projection
    build_feat<<<(BS * 640 + 255) / 256, 256>>>(intra_x, wr, p_vv, p_vh, p_ih, p_feat);
    gemm_tc<<<dim3(8, 4), 256>>>(BS, 256, 640, p_feat, 640, p_Wln, 640, ln_b, out, 256);
}